// round 7
// baseline (speedup 1.0000x reference)
#include <cuda_runtime.h>
#include <math.h>

#define NQ   6
#define DIM  64
#define SPT  128        // samples per iteration per CTA
#define PW   72         // weight pitch (words), half-shift layout
#define PA   136        // aT pitch (words)

typedef unsigned long long ull;

__device__ float g_CRT[DIM * DIM];   // [j][i]
__device__ float g_CIT[DIM * DIM];   // [j][i]
__device__ float g_Mz[5 * DIM];      // [o][i]

__device__ __forceinline__ void ffma2(ull &d, ull a, ull b) {
    asm("fma.rn.f32x2 %0, %1, %2, %0;" : "+l"(d) : "l"(a), "l"(b));
}
__device__ __forceinline__ ull dup2(float v) {
    ull r; asm("mov.b64 %0, {%1, %1};" : "=l"(r) : "f"(v)); return r;
}
// half-shift: words i>=32 shifted +4 so 8 lanes at 32B stride hit distinct bank quads
__device__ __forceinline__ int ish(int i) { return i + ((i >> 5) << 2); }

__device__ __forceinline__ int ring_map(int r, int i) {
    int v = i;
    for (int w = NQ - 1; w >= 0; --w) {
        int t = (w + r) % NQ;
        v ^= ((v >> (NQ - 1 - w)) & 1) << (NQ - 1 - t);
    }
    return v;
}

// One block, 64 threads. Thread j owns column j of C.
__global__ void setup_kernel(const float* __restrict__ th_sh,
                             const float* __restrict__ th_tk,
                             const float* __restrict__ Wc) {
    __shared__ float2 C[DIM][DIM];
    int j = threadIdx.x;
    if (j >= DIM) return;
    for (int i = 0; i < DIM; i++) C[i][j] = make_float2(i == j ? 1.f : 0.f, 0.f);

    const float* TH[3] = { th_sh, th_sh + NQ * 3, th_tk };
    const int    RS[3] = { 1, 2, 1 };

    for (int l = 0; l < 3; l++) {
        const float* th = TH[l];
        for (int w = 0; w < NQ; w++) {
            float phi = th[w * 3 + 0], te = th[w * 3 + 1], om = th[w * 3 + 2];
            float sth, cth; sincosf(0.5f * te, &sth, &cth);
            float a = 0.5f * (phi + om), b = 0.5f * (phi - om);
            float sa, ca, sb, cb;
            sincosf(a, &sa, &ca);
            sincosf(b, &sb, &cb);
            float2 R00 = make_float2( ca * cth, -sa * cth);
            float2 R01 = make_float2(-cb * sth, -sb * sth);
            float2 R10 = make_float2( cb * sth, -sb * sth);
            float2 R11 = make_float2( ca * cth,  sa * cth);
            int bit = 1 << (NQ - 1 - w);
            for (int i0 = 0; i0 < DIM; i0++) {
                if (i0 & bit) continue;
                int i1 = i0 | bit;
                float2 v0 = C[i0][j], v1 = C[i1][j];
                C[i0][j] = make_float2(
                    R00.x * v0.x - R00.y * v0.y + R01.x * v1.x - R01.y * v1.y,
                    R00.x * v0.y + R00.y * v0.x + R01.x * v1.y + R01.y * v1.x);
                C[i1][j] = make_float2(
                    R10.x * v0.x - R10.y * v0.y + R11.x * v1.x - R11.y * v1.y,
                    R10.x * v0.y + R10.y * v0.x + R11.x * v1.y + R11.y * v1.x);
            }
        }
        float2 tmp[DIM];
        for (int i = 0; i < DIM; i++) tmp[i] = C[ring_map(RS[l], i)][j];
        for (int i = 0; i < DIM; i++) C[i][j] = tmp[i];
    }
    for (int i = 0; i < DIM; i++) {
        g_CRT[j * DIM + i] = C[i][j].x;
        g_CIT[j * DIM + i] = C[i][j].y;
    }
    for (int o = 0; o < 5; o++) {
        float s = 0.f;
        for (int q = 0; q < NQ; q++) {
            float zs = ((j >> (NQ - 1 - q)) & 1) ? -1.f : 1.f;
            s += zs * Wc[o * NQ + q];
        }
        g_Mz[o * DIM + j] = s;
    }
}

// smem layout (floats)
#define OFF_W1T  0
#define OFF_CRT  (OFF_W1T + DIM * PW)          // 4608
#define OFF_CIT  (OFF_CRT + DIM * PW)          // 9216
#define OFF_MZT  (OFF_CIT + DIM * PW)          // 13824
#define OFF_W2   (OFF_MZT + 5 * PW)            // 14184
#define OFF_B1   (OFF_W2 + NQ * PW)            // 14616
#define OFF_LNG  (OFF_B1 + DIM)
#define OFF_LNB  (OFF_LNG + DIM)
#define OFF_B2   (OFF_LNB + DIM)               // 14808
#define OFF_BC   (OFF_B2 + 8)                  // 14816
#define OFF_AT   (OFF_BC + 8)                  // 14824 (mult of 4 -> 16B aligned)
#define OFF_VEC  (OFF_AT + DIM * PA)           // 23528
#define SMEM_FLOATS (OFF_VEC + SPT * 13)       // 25192 -> ~100.8 KB

__global__ __launch_bounds__(256, 2)
void qmaml_main_kernel(const float* __restrict__ x,
                       const float* __restrict__ W1,
                       const float* __restrict__ b1,
                       const float* __restrict__ lng,
                       const float* __restrict__ lnb,
                       const float* __restrict__ W2,
                       const float* __restrict__ b2,
                       const float* __restrict__ bc,
                       float* __restrict__ out,
                       int nIter) {
    extern __shared__ float sm[];
    float* sW1T = sm + OFF_W1T;   // [j][ish(i)]
    float* sCRT = sm + OFF_CRT;
    float* sCIT = sm + OFF_CIT;
    float* sMzT = sm + OFF_MZT;   // [o][ish(i)]
    float* sW2  = sm + OFF_W2;    // [q][ish(i)]
    float* sB1  = sm + OFF_B1;
    float* sLnG = sm + OFF_LNG;
    float* sLnB = sm + OFF_LNB;
    float* sB2  = sm + OFF_B2;
    float* sBc  = sm + OFF_BC;
    float* sAT  = sm + OFF_AT;    // [j][(s + (j&60)) & 127] pitch 136
    float* sVec = sm + OFF_VEC;   // [s][13]

    const int tid = threadIdx.x;

    // ---- load weights once ----
    for (int idx = tid; idx < DIM * DIM; idx += 256) {
        int j = idx >> 6, i = idx & 63;
        int d = j * PW + ish(i);
        sW1T[d] = W1[i * DIM + j];    // W1 [i][j] row-major -> [j][i]
        sCRT[d] = g_CRT[idx];         // already [j][i]
        sCIT[d] = g_CIT[idx];
    }
    for (int idx = tid; idx < 5 * DIM; idx += 256) {
        int o = idx >> 6, i = idx & 63;
        sMzT[o * PW + ish(i)] = g_Mz[idx];
    }
    for (int idx = tid; idx < NQ * DIM; idx += 256) {
        int q = idx >> 6, i = idx & 63;
        sW2[q * PW + ish(i)] = W2[idx];
    }
    if (tid < DIM) { sB1[tid] = b1[tid]; sLnG[tid] = lng[tid]; sLnB[tid] = lnb[tid]; }
    if (tid < NQ) sB2[tid] = b2[tid];
    if (tid < 5) sBc[tid] = bc[tid];
    __syncthreads();

    const int tx = tid & 7, ty = tid >> 3;   // tx over i (8), ty over s (32)
    const int i0 = tx * 8, s0 = ty * 4;
    const int ish0 = ish(i0);

    for (int iter = blockIdx.x; iter < nIter; iter += gridDim.x) {
        const float4* xg = (const float4*)(x + (size_t)iter * SPT * DIM);

        // ---- stage X^T into sAT[j][(s + (j&60)) & 127] ----
        #pragma unroll
        for (int t = 0; t < 8; t++) {
            int idx = tid + t * 256;             // 2048 float4
            float4 v = xg[idx];
            int s = idx >> 4, j0 = (idx & 15) << 2;
            int rs = (s + j0) & 127;             // rot_j = j&60 == j0 here
            sAT[(j0 + 0) * PA + rs] = v.x;
            sAT[(j0 + 1) * PA + rs] = v.y;
            sAT[(j0 + 2) * PA + rs] = v.z;
            sAT[(j0 + 3) * PA + rs] = v.w;
        }
        __syncthreads();

        // ---- GEMM1: acc[s][ipair] over j ----
        ull acc[4][4];
        #pragma unroll
        for (int s = 0; s < 4; s++)
            #pragma unroll
            for (int q = 0; q < 4; q++) acc[s][q] = 0ull;

        #pragma unroll 4
        for (int j = 0; j < DIM; j++) {
            const float* ap = sAT + j * PA + ((s0 + (j & 60)) & 127);
            float4 a = *(const float4*)ap;
            const float* bp = sW1T + j * PW + ish0;
            ulonglong2 b01 = *(const ulonglong2*)bp;
            ulonglong2 b23 = *(const ulonglong2*)(bp + 4);
            ull ad[4];
            ad[0] = dup2(a.x); ad[1] = dup2(a.y); ad[2] = dup2(a.z); ad[3] = dup2(a.w);
            #pragma unroll
            for (int s = 0; s < 4; s++) {
                ffma2(acc[s][0], ad[s], b01.x);
                ffma2(acc[s][1], ad[s], b01.y);
                ffma2(acc[s][2], ad[s], b23.x);
                ffma2(acc[s][3], ad[s], b23.y);
            }
        }

        // ---- bias + relu + LayerNorm (registers + shfl over tx octet) ----
        float h[4][8];
        {
            float bb[8], gg[8], be[8];
            #pragma unroll
            for (int c = 0; c < 8; c++) {
                bb[c] = sB1[i0 + c]; gg[c] = sLnG[i0 + c]; be[c] = sLnB[i0 + c];
            }
            #pragma unroll
            for (int s = 0; s < 4; s++)
                #pragma unroll
                for (int q = 0; q < 4; q++) {
                    float2 f = *(float2*)&acc[s][q];
                    h[s][2 * q]     = fmaxf(f.x + bb[2 * q], 0.f);
                    h[s][2 * q + 1] = fmaxf(f.y + bb[2 * q + 1], 0.f);
                }
            float su[4], sq[4];
            #pragma unroll
            for (int s = 0; s < 4; s++) {
                float a = 0.f, b = 0.f;
                #pragma unroll
                for (int c = 0; c < 8; c++) { a += h[s][c]; b += h[s][c] * h[s][c]; }
                su[s] = a; sq[s] = b;
            }
            #pragma unroll
            for (int off = 1; off < 8; off <<= 1)
                #pragma unroll
                for (int s = 0; s < 4; s++) {
                    su[s] += __shfl_xor_sync(0xffffffffu, su[s], off);
                    sq[s] += __shfl_xor_sync(0xffffffffu, sq[s], off);
                }
            #pragma unroll
            for (int s = 0; s < 4; s++) {
                float mu  = su[s] * (1.f / DIM);
                float var = sq[s] * (1.f / DIM) - mu * mu;
                float inv = rsqrtf(var + 1e-5f);
                #pragma unroll
                for (int c = 0; c < 8; c++)
                    h[s][c] = (h[s][c] - mu) * inv * gg[c] + be[c];
            }
        }

        // ---- z = tanh(Hn @ W2^T + b2) -> vec; full butterfly, lanes tx<4 store ----
        {
            #pragma unroll
            for (int q = 0; q < NQ; q++) {
                const float* wp = sW2 + q * PW + ish0;
                float4 wa = *(const float4*)wp;
                float4 wb = *(const float4*)(wp + 4);
                float w[8] = { wa.x, wa.y, wa.z, wa.w, wb.x, wb.y, wb.z, wb.w };
                float v[4];
                #pragma unroll
                for (int s = 0; s < 4; s++) {
                    float d = 0.f;
                    #pragma unroll
                    for (int c = 0; c < 8; c++) d += h[s][c] * w[c];
                    v[s] = d;
                }
                #pragma unroll
                for (int off = 1; off < 8; off <<= 1)
                    #pragma unroll
                    for (int s = 0; s < 4; s++)
                        v[s] += __shfl_xor_sync(0xffffffffu, v[s], off);
                if (tx < 4) {
                    int sg = s0 + tx;
                    float z    = tanhf(v[tx & 3] + sB2[q]);
                    float half = 1.5707963267948966f * z;
                    float sn, cs;
                    __sincosf(half, &sn, &cs);
                    sVec[sg * 13 + 2 * q]     = cs;
                    sVec[sg * 13 + 2 * q + 1] = sn;
                }
            }
        }
        __syncthreads();

        // ---- psi0: 2 threads per sample, 32 amplitudes each, store transposed ----
        {
            int s = tid >> 1, half = tid & 1;
            const float* vv = sVec + s * 13;
            float t1 = vv[half];          // qubit0 bit = half
            float t2[2], t4[4], t8[8], t16[16], t32[32];
            t2[0] = t1 * vv[2]; t2[1] = t1 * vv[3];
            #pragma unroll
            for (int k = 0; k < 2; k++) { t4[2*k] = t2[k]*vv[4]; t4[2*k+1] = t2[k]*vv[5]; }
            #pragma unroll
            for (int k = 0; k < 4; k++) { t8[2*k] = t4[k]*vv[6]; t8[2*k+1] = t4[k]*vv[7]; }
            #pragma unroll
            for (int k = 0; k < 8; k++) { t16[2*k] = t8[k]*vv[8]; t16[2*k+1] = t8[k]*vv[9]; }
            #pragma unroll
            for (int k = 0; k < 16; k++) { t32[2*k] = t16[k]*vv[10]; t32[2*k+1] = t16[k]*vv[11]; }
            int jb = half << 5;
            #pragma unroll
            for (int jj = 0; jj < 32; jj++) {
                int j = jb + jj;
                sAT[j * PA + ((s + (j & 60)) & 127)] = t32[jj];
            }
        }
        __syncthreads();

        // ---- GEMM2/3: psiR/psiI = psi0 @ C^T ----
        ull aR[4][4], aI[4][4];
        #pragma unroll
        for (int s = 0; s < 4; s++)
            #pragma unroll
            for (int q = 0; q < 4; q++) { aR[s][q] = 0ull; aI[s][q] = 0ull; }

        #pragma unroll 4
        for (int j = 0; j < DIM; j++) {
            const float* ap = sAT + j * PA + ((s0 + (j & 60)) & 127);
            float4 a = *(const float4*)ap;
            const float* rp = sCRT + j * PW + ish0;
            const float* ip = sCIT + j * PW + ish0;
            ulonglong2 r01 = *(const ulonglong2*)rp;
            ulonglong2 r23 = *(const ulonglong2*)(rp + 4);
            ulonglong2 i01 = *(const ulonglong2*)ip;
            ulonglong2 i23 = *(const ulonglong2*)(ip + 4);
            ull ad[4];
            ad[0] = dup2(a.x); ad[1] = dup2(a.y); ad[2] = dup2(a.z); ad[3] = dup2(a.w);
            #pragma unroll
            for (int s = 0; s < 4; s++) {
                ffma2(aR[s][0], ad[s], r01.x);
                ffma2(aR[s][1], ad[s], r01.y);
                ffma2(aR[s][2], ad[s], r23.x);
                ffma2(aR[s][3], ad[s], r23.y);
                ffma2(aI[s][0], ad[s], i01.x);
                ffma2(aI[s][1], ad[s], i01.y);
                ffma2(aI[s][2], ad[s], i23.x);
                ffma2(aI[s][3], ad[s], i23.y);
            }
        }

        // ---- probs -> Mz partials -> butterfly -> gmem ----
        {
            ulonglong2 mza[5], mzb[5];
            #pragma unroll
            for (int o = 0; o < 5; o++) {
                const float* mp = sMzT + o * PW + ish0;
                mza[o] = *(const ulonglong2*)mp;
                mzb[o] = *(const ulonglong2*)(mp + 4);
            }
            float vals[4][5];
            #pragma unroll
            for (int s = 0; s < 4; s++) {
                ull pp[4];
                #pragma unroll
                for (int q = 0; q < 4; q++) {
                    pp[q] = 0ull;
                    ffma2(pp[q], aR[s][q], aR[s][q]);
                    ffma2(pp[q], aI[s][q], aI[s][q]);
                }
                #pragma unroll
                for (int o = 0; o < 5; o++) {
                    ull a5 = 0ull;
                    ffma2(a5, pp[0], mza[o].x);
                    ffma2(a5, pp[1], mza[o].y);
                    ffma2(a5, pp[2], mzb[o].x);
                    ffma2(a5, pp[3], mzb[o].y);
                    float2 f = *(float2*)&a5;
                    vals[s][o] = f.x + f.y;
                }
            }
            #pragma unroll
            for (int off = 1; off < 8; off <<= 1)
                #pragma unroll
                for (int s = 0; s < 4; s++)
                    #pragma unroll
                    for (int o = 0; o < 5; o++)
                        vals[s][o] += __shfl_xor_sync(0xffffffffu, vals[s][o], off);
            if (tx < 4) {
                int sg = iter * SPT + s0 + tx;
                #pragma unroll
                for (int o = 0; o < 5; o++)
                    out[(size_t)sg * 5 + o] = vals[tx & 3][o] + sBc[o];
            }
        }
        __syncthreads();   // protect sAT/sVec before next iteration
    }
}

extern "C" void kernel_launch(void* const* d_in, const int* in_sizes, int n_in,
                              void* d_out, int out_size) {
    const float* x     = (const float*)d_in[0];
    const float* W1    = (const float*)d_in[1];
    const float* b1    = (const float*)d_in[2];
    const float* ln_g  = (const float*)d_in[3];
    const float* ln_b  = (const float*)d_in[4];
    const float* W2    = (const float*)d_in[5];
    const float* b2    = (const float*)d_in[6];
    const float* th_sh = (const float*)d_in[7];
    const float* th_tk = (const float*)d_in[8];
    const float* Wc    = (const float*)d_in[9];
    const float* bc    = (const float*)d_in[10];
    float* out = (float*)d_out;

    int B = in_sizes[0] / DIM;
    int nIter = B / SPT;

    setup_kernel<<<1, 64>>>(th_sh, th_tk, Wc);

    size_t smem = (size_t)SMEM_FLOATS * sizeof(float);
    cudaFuncSetAttribute(qmaml_main_kernel,
                         cudaFuncAttributeMaxDynamicSharedMemorySize, (int)smem);

    int grid = 296;
    if (grid > nIter) grid = nIter;
    qmaml_main_kernel<<<grid, 256, smem>>>(x, W1, b1, ln_g, ln_b, W2, b2, bc,
                                           out, nIter);
}

// round 8
// speedup vs baseline: 1.0133x; 1.0133x over previous
#include <cuda_runtime.h>
#include <math.h>

#define NQ   6
#define DIM  64
#define SPT  256        // samples per iteration per CTA (128 per half)
#define HS   128        // samples per half
#define PW   72         // weight pitch (words), half-shift layout
#define PA   136        // aT pitch: 128 samples + 8 mirror words

typedef unsigned long long ull;

__device__ float g_CRT[DIM * DIM];   // [j][i]
__device__ float g_CIT[DIM * DIM];   // [j][i]
__device__ float g_Mz[5 * DIM];      // [o][i]

__device__ __forceinline__ void ffma2(ull &d, ull a, ull b) {
    asm("fma.rn.f32x2 %0, %1, %2, %0;" : "+l"(d) : "l"(a), "l"(b));
}
__device__ __forceinline__ ull dup2(float v) {
    ull r; asm("mov.b64 %0, {%1, %1};" : "=l"(r) : "f"(v)); return r;
}
// half-shift: words i>=32 shifted +4 so 8 lanes at 32B stride hit distinct bank quads
__device__ __forceinline__ int ish(int i) { return i + ((i >> 5) << 2); }

__device__ __forceinline__ void hbar(int half) {
    asm volatile("bar.sync %0, 128;" :: "r"(1 + half) : "memory");
}

__device__ __forceinline__ float fast_tanh(float x) {
    float e = __expf(-2.f * fabsf(x));
    float t = __fdividef(1.f - e, 1.f + e);
    return copysignf(t, x);
}

__device__ __forceinline__ int ring_map(int r, int i) {
    int v = i;
    for (int w = NQ - 1; w >= 0; --w) {
        int t = (w + r) % NQ;
        v ^= ((v >> (NQ - 1 - w)) & 1) << (NQ - 1 - t);
    }
    return v;
}

// One block, 64 threads. Thread j owns column j of C.
__global__ void setup_kernel(const float* __restrict__ th_sh,
                             const float* __restrict__ th_tk,
                             const float* __restrict__ Wc) {
    __shared__ float2 C[DIM][DIM];
    int j = threadIdx.x;
    if (j >= DIM) return;
    for (int i = 0; i < DIM; i++) C[i][j] = make_float2(i == j ? 1.f : 0.f, 0.f);

    const float* TH[3] = { th_sh, th_sh + NQ * 3, th_tk };
    const int    RS[3] = { 1, 2, 1 };

    for (int l = 0; l < 3; l++) {
        const float* th = TH[l];
        for (int w = 0; w < NQ; w++) {
            float phi = th[w * 3 + 0], te = th[w * 3 + 1], om = th[w * 3 + 2];
            float sth, cth; sincosf(0.5f * te, &sth, &cth);
            float a = 0.5f * (phi + om), b = 0.5f * (phi - om);
            float sa, ca, sb, cb;
            sincosf(a, &sa, &ca);
            sincosf(b, &sb, &cb);
            float2 R00 = make_float2( ca * cth, -sa * cth);
            float2 R01 = make_float2(-cb * sth, -sb * sth);
            float2 R10 = make_float2( cb * sth, -sb * sth);
            float2 R11 = make_float2( ca * cth,  sa * cth);
            int bit = 1 << (NQ - 1 - w);
            for (int i0 = 0; i0 < DIM; i0++) {
                if (i0 & bit) continue;
                int i1 = i0 | bit;
                float2 v0 = C[i0][j], v1 = C[i1][j];
                C[i0][j] = make_float2(
                    R00.x * v0.x - R00.y * v0.y + R01.x * v1.x - R01.y * v1.y,
                    R00.x * v0.y + R00.y * v0.x + R01.x * v1.y + R01.y * v1.x);
                C[i1][j] = make_float2(
                    R10.x * v0.x - R10.y * v0.y + R11.x * v1.x - R11.y * v1.y,
                    R10.x * v0.y + R10.y * v0.x + R11.x * v1.y + R11.y * v1.x);
            }
        }
        float2 tmp[DIM];
        for (int i = 0; i < DIM; i++) tmp[i] = C[ring_map(RS[l], i)][j];
        for (int i = 0; i < DIM; i++) C[i][j] = tmp[i];
    }
    for (int i = 0; i < DIM; i++) {
        g_CRT[j * DIM + i] = C[i][j].x;
        g_CIT[j * DIM + i] = C[i][j].y;
    }
    for (int o = 0; o < 5; o++) {
        float s = 0.f;
        for (int q = 0; q < NQ; q++) {
            float zs = ((j >> (NQ - 1 - q)) & 1) ? -1.f : 1.f;
            s += zs * Wc[o * NQ + q];
        }
        g_Mz[o * DIM + j] = s;
    }
}

// smem layout (floats) — weights shared by both halves; aT/vec per half
#define OFF_W1T  0
#define OFF_CRT  (OFF_W1T + DIM * PW)          // 4608
#define OFF_CIT  (OFF_CRT + DIM * PW)          // 9216
#define OFF_MZT  (OFF_CIT + DIM * PW)          // 13824
#define OFF_W2   (OFF_MZT + 5 * PW)            // 14184
#define OFF_B1   (OFF_W2 + NQ * PW)            // 14616
#define OFF_LNG  (OFF_B1 + DIM)
#define OFF_LNB  (OFF_LNG + DIM)
#define OFF_B2   (OFF_LNB + DIM)               // 14808
#define OFF_BC   (OFF_B2 + 8)                  // 14816
#define OFF_AT   (OFF_BC + 8)                  // 14824
#define AT_HALF  (DIM * PA)                    // 8704 per half
#define OFF_VEC  (OFF_AT + 2 * AT_HALF)        // 32232
#define VEC_HALF (HS * 13)                     // 1664 per half
#define SMEM_FLOATS (OFF_VEC + 2 * VEC_HALF)   // 35560 -> ~139 KB

// transpose-reduce: sum v[s] over 8 tx lanes; lane tx returns value for s == tx
__device__ __forceinline__ float txreduce8(float* v, int tx) {
    #pragma unroll
    for (int a = 0; a < 8; a++) v[a] += __shfl_xor_sync(0xffffffffu, v[a], 4);
    float v4[4];
    #pragma unroll
    for (int a = 0; a < 4; a++) v4[a] = (tx & 4) ? v[4 + a] : v[a];
    #pragma unroll
    for (int a = 0; a < 4; a++) v4[a] += __shfl_xor_sync(0xffffffffu, v4[a], 2);
    float v2[2];
    #pragma unroll
    for (int a = 0; a < 2; a++) v2[a] = (tx & 2) ? v4[2 + a] : v4[a];
    #pragma unroll
    for (int a = 0; a < 2; a++) v2[a] += __shfl_xor_sync(0xffffffffu, v2[a], 1);
    return (tx & 1) ? v2[1] : v2[0];
}

__global__ __launch_bounds__(256, 1)
void qmaml_main_kernel(const float* __restrict__ x,
                       const float* __restrict__ W1,
                       const float* __restrict__ b1,
                       const float* __restrict__ lng,
                       const float* __restrict__ lnb,
                       const float* __restrict__ W2,
                       const float* __restrict__ b2,
                       const float* __restrict__ bc,
                       float* __restrict__ out,
                       int nIter) {
    extern __shared__ float sm[];
    float* sW1T = sm + OFF_W1T;   // [j][ish(i)]
    float* sCRT = sm + OFF_CRT;
    float* sCIT = sm + OFF_CIT;
    float* sMzT = sm + OFF_MZT;   // [o][ish(i)]
    float* sW2  = sm + OFF_W2;    // [q][ish(i)]
    float* sB1  = sm + OFF_B1;
    float* sLnG = sm + OFF_LNG;
    float* sLnB = sm + OFF_LNB;
    float* sB2  = sm + OFF_B2;
    float* sBc  = sm + OFF_BC;

    const int tid  = threadIdx.x;
    const int half = tid >> 7;          // 0 or 1
    const int lt   = tid & 127;         // local tid within half

    float* sAT  = sm + OFF_AT  + half * AT_HALF;   // [j][rot(s)] pitch 136, mirror pad
    float* sVec = sm + OFF_VEC + half * VEC_HALF;  // [s][13]

    // ---- load shared weights once (whole CTA) ----
    for (int idx = tid; idx < DIM * DIM; idx += 256) {
        int j = idx >> 6, i = idx & 63;
        int d = j * PW + ish(i);
        sW1T[d] = W1[i * DIM + j];    // W1 [i][j] row-major -> [j][i]
        sCRT[d] = g_CRT[idx];         // already [j][i]
        sCIT[d] = g_CIT[idx];
    }
    for (int idx = tid; idx < 5 * DIM; idx += 256) {
        int o = idx >> 6, i = idx & 63;
        sMzT[o * PW + ish(i)] = g_Mz[idx];
    }
    for (int idx = tid; idx < NQ * DIM; idx += 256) {
        int q = idx >> 6, i = idx & 63;
        sW2[q * PW + ish(i)] = W2[idx];
    }
    if (tid < DIM) { sB1[tid] = b1[tid]; sLnG[tid] = lng[tid]; sLnB[tid] = lnb[tid]; }
    if (tid < NQ) sB2[tid] = b2[tid];
    if (tid < 5) sBc[tid] = bc[tid];
    __syncthreads();

    const int tx = lt & 7, ty = lt >> 3;   // tx over i (8), ty over s (16)
    const int i0 = tx * 8, s0 = ty * 8;
    const int ish0 = ish(i0);

    for (int iter = blockIdx.x; iter < nIter; iter += gridDim.x) {
        const float4* xg = (const float4*)(x + ((size_t)iter * SPT + half * HS) * DIM);

        // ---- stage X^T into sAT[j][(s + (j&60)) & 127] with mirror pad ----
        #pragma unroll
        for (int t = 0; t < 16; t++) {
            int idx = lt + t * 128;              // 2048 float4 per half
            float4 v = xg[idx];
            int s = idx >> 4, j0 = (idx & 15) << 2;
            int rs = (s + j0) & 127;             // rot_j = j&60 == j0 here
            float* p0 = sAT + (j0 + 0) * PA + rs;
            float* p1 = sAT + (j0 + 1) * PA + rs;
            float* p2 = sAT + (j0 + 2) * PA + rs;
            float* p3 = sAT + (j0 + 3) * PA + rs;
            *p0 = v.x; *p1 = v.y; *p2 = v.z; *p3 = v.w;
            if (rs < 4) { p0[128] = v.x; p1[128] = v.y; p2[128] = v.z; p3[128] = v.w; }
        }
        hbar(half);

        // ---- GEMM1: acc[s][ipair] over j ----
        ull acc[8][4];
        #pragma unroll
        for (int s = 0; s < 8; s++)
            #pragma unroll
            for (int q = 0; q < 4; q++) acc[s][q] = 0ull;

        #pragma unroll 4
        for (int j = 0; j < DIM; j++) {
            const float* ap = sAT + j * PA + ((s0 + (j & 60)) & 127);
            float4 al = *(const float4*)ap;
            float4 ah = *(const float4*)(ap + 4);
            const float* bp = sW1T + j * PW + ish0;
            ulonglong2 b01 = *(const ulonglong2*)bp;
            ulonglong2 b23 = *(const ulonglong2*)(bp + 4);
            ull ad[8];
            ad[0] = dup2(al.x); ad[1] = dup2(al.y); ad[2] = dup2(al.z); ad[3] = dup2(al.w);
            ad[4] = dup2(ah.x); ad[5] = dup2(ah.y); ad[6] = dup2(ah.z); ad[7] = dup2(ah.w);
            #pragma unroll
            for (int s = 0; s < 8; s++) {
                ffma2(acc[s][0], ad[s], b01.x);
                ffma2(acc[s][1], ad[s], b01.y);
                ffma2(acc[s][2], ad[s], b23.x);
                ffma2(acc[s][3], ad[s], b23.y);
            }
        }

        // ---- bias + relu + LayerNorm (registers + shfl over tx octet) ----
        float h[8][8];
        {
            float bb[8], gg[8], be[8];
            #pragma unroll
            for (int c = 0; c < 8; c++) {
                bb[c] = sB1[i0 + c]; gg[c] = sLnG[i0 + c]; be[c] = sLnB[i0 + c];
            }
            #pragma unroll
            for (int s = 0; s < 8; s++)
                #pragma unroll
                for (int q = 0; q < 4; q++) {
                    float2 f = *(float2*)&acc[s][q];
                    h[s][2 * q]     = fmaxf(f.x + bb[2 * q], 0.f);
                    h[s][2 * q + 1] = fmaxf(f.y + bb[2 * q + 1], 0.f);
                }
            float su[8], sq[8];
            #pragma unroll
            for (int s = 0; s < 8; s++) {
                float a = 0.f, b = 0.f;
                #pragma unroll
                for (int c = 0; c < 8; c++) { a += h[s][c]; b += h[s][c] * h[s][c]; }
                su[s] = a; sq[s] = b;
            }
            #pragma unroll
            for (int off = 1; off < 8; off <<= 1)
                #pragma unroll
                for (int s = 0; s < 8; s++) {
                    su[s] += __shfl_xor_sync(0xffffffffu, su[s], off);
                    sq[s] += __shfl_xor_sync(0xffffffffu, sq[s], off);
                }
            #pragma unroll
            for (int s = 0; s < 8; s++) {
                float mu  = su[s] * (1.f / DIM);
                float var = sq[s] * (1.f / DIM) - mu * mu;
                float inv = rsqrtf(var + 1e-5f);
                #pragma unroll
                for (int c = 0; c < 8; c++)
                    h[s][c] = (h[s][c] - mu) * inv * gg[c] + be[c];
            }
        }

        // ---- z = tanh(Hn @ W2^T + b2): partials + transpose-reduce ----
        {
            float zp[8][NQ];
            #pragma unroll
            for (int q = 0; q < NQ; q++) {
                const float* wp = sW2 + q * PW + ish0;
                float4 wa = *(const float4*)wp;
                float4 wb = *(const float4*)(wp + 4);
                float w[8] = { wa.x, wa.y, wa.z, wa.w, wb.x, wb.y, wb.z, wb.w };
                #pragma unroll
                for (int s = 0; s < 8; s++) {
                    float d = 0.f;
                    #pragma unroll
                    for (int c = 0; c < 8; c++) d += h[s][c] * w[c];
                    zp[s][q] = d;
                }
            }
            int sg = s0 + tx;   // lane tx owns sample s0+tx after reduce
            #pragma unroll
            for (int q = 0; q < NQ; q++) {
                float v[8];
                #pragma unroll
                for (int s = 0; s < 8; s++) v[s] = zp[s][q];
                float zs = txreduce8(v, tx);
                float z    = fast_tanh(zs + sB2[q]);
                float hh   = 1.5707963267948966f * z;
                float sn, cs;
                __sincosf(hh, &sn, &cs);
                sVec[sg * 13 + 2 * q]     = cs;
                sVec[sg * 13 + 2 * q + 1] = sn;
            }
        }
        hbar(half);

        // ---- psi0: thread = sample, build 64 amplitudes, store transposed ----
        {
            int s = lt;
            const float* vv = sVec + s * 13;
            float p1[2], p2[4], p3[8], p4[16], p5[32], p6[64];
            p1[0] = vv[0]; p1[1] = vv[1];
            #pragma unroll
            for (int k = 0; k < 2; k++) { p2[2*k] = p1[k]*vv[2]; p2[2*k+1] = p1[k]*vv[3]; }
            #pragma unroll
            for (int k = 0; k < 4; k++) { p3[2*k] = p2[k]*vv[4]; p3[2*k+1] = p2[k]*vv[5]; }
            #pragma unroll
            for (int k = 0; k < 8; k++) { p4[2*k] = p3[k]*vv[6]; p4[2*k+1] = p3[k]*vv[7]; }
            #pragma unroll
            for (int k = 0; k < 16; k++) { p5[2*k] = p4[k]*vv[8]; p5[2*k+1] = p4[k]*vv[9]; }
            #pragma unroll
            for (int k = 0; k < 32; k++) { p6[2*k] = p5[k]*vv[10]; p6[2*k+1] = p5[k]*vv[11]; }
            #pragma unroll
            for (int j = 0; j < DIM; j++) {
                int rs = (s + (j & 60)) & 127;
                sAT[j * PA + rs] = p6[j];
                if (rs < 4) sAT[j * PA + rs + 128] = p6[j];
            }
        }
        hbar(half);

        // ---- GEMM2/3: psiR/psiI = psi0 @ C^T ----
        ull aR[8][4], aI[8][4];
        #pragma unroll
        for (int s = 0; s < 8; s++)
            #pragma unroll
            for (int q = 0; q < 4; q++) { aR[s][q] = 0ull; aI[s][q] = 0ull; }

        #pragma unroll 4
        for (int j = 0; j < DIM; j++) {
            const float* ap = sAT + j * PA + ((s0 + (j & 60)) & 127);
            float4 al = *(const float4*)ap;
            float4 ah = *(const float4*)(ap + 4);
            const float* rp = sCRT + j * PW + ish0;
            const float* ip = sCIT + j * PW + ish0;
            ulonglong2 r01 = *(const ulonglong2*)rp;
            ulonglong2 r23 = *(const ulonglong2*)(rp + 4);
            ulonglong2 i01 = *(const ulonglong2*)ip;
            ulonglong2 i23 = *(const ulonglong2*)(ip + 4);
            ull ad[8];
            ad[0] = dup2(al.x); ad[1] = dup2(al.y); ad[2] = dup2(al.z); ad[3] = dup2(al.w);
            ad[4] = dup2(ah.x); ad[5] = dup2(ah.y); ad[6] = dup2(ah.z); ad[7] = dup2(ah.w);
            #pragma unroll
            for (int s = 0; s < 8; s++) {
                ffma2(aR[s][0], ad[s], r01.x);
                ffma2(aR[s][1], ad[s], r01.y);
                ffma2(aR[s][2], ad[s], r23.x);
                ffma2(aR[s][3], ad[s], r23.y);
                ffma2(aI[s][0], ad[s], i01.x);
                ffma2(aI[s][1], ad[s], i01.y);
                ffma2(aI[s][2], ad[s], i23.x);
                ffma2(aI[s][3], ad[s], i23.y);
            }
        }

        // ---- probs (packed) -> Mz partials -> transpose-reduce -> gmem ----
        {
            ulonglong2 mza[5], mzb[5];
            #pragma unroll
            for (int o = 0; o < 5; o++) {
                const float* mp = sMzT + o * PW + ish0;
                mza[o] = *(const ulonglong2*)mp;
                mzb[o] = *(const ulonglong2*)(mp + 4);
            }
            float vals[8][5];
            #pragma unroll
            for (int s = 0; s < 8; s++) {
                ull pp[4];
                #pragma unroll
                for (int q = 0; q < 4; q++) {
                    pp[q] = 0ull;
                    ffma2(pp[q], aR[s][q], aR[s][q]);
                    ffma2(pp[q], aI[s][q], aI[s][q]);
                }
                #pragma unroll
                for (int o = 0; o < 5; o++) {
                    ull a5 = 0ull;
                    ffma2(a5, pp[0], mza[o].x);
                    ffma2(a5, pp[1], mza[o].y);
                    ffma2(a5, pp[2], mzb[o].x);
                    ffma2(a5, pp[3], mzb[o].y);
                    float2 f = *(float2*)&a5;
                    vals[s][o] = f.x + f.y;
                }
            }
            int sg = iter * SPT + half * HS + s0 + tx;
            #pragma unroll
            for (int o = 0; o < 5; o++) {
                float v[8];
                #pragma unroll
                for (int s = 0; s < 8; s++) v[s] = vals[s][o];
                float r = txreduce8(v, tx);
                out[(size_t)sg * 5 + o] = r + sBc[o];
            }
        }
        hbar(half);   // protect sAT/sVec before next iteration
    }
}

extern "C" void kernel_launch(void* const* d_in, const int* in_sizes, int n_in,
                              void* d_out, int out_size) {
    const float* x     = (const float*)d_in[0];
    const float* W1    = (const float*)d_in[1];
    const float* b1    = (const float*)d_in[2];
    const float* ln_g  = (const float*)d_in[3];
    const float* ln_b  = (const float*)d_in[4];
    const float* W2    = (const float*)d_in[5];
    const float* b2    = (const float*)d_in[6];
    const float* th_sh = (const float*)d_in[7];
    const float* th_tk = (const float*)d_in[8];
    const float* Wc    = (const float*)d_in[9];
    const float* bc    = (const float*)d_in[10];
    float* out = (float*)d_out;

    int B = in_sizes[0] / DIM;
    int nIter = B / SPT;

    setup_kernel<<<1, 64>>>(th_sh, th_tk, Wc);

    size_t smem = (size_t)SMEM_FLOATS * sizeof(float);
    cudaFuncSetAttribute(qmaml_main_kernel,
                         cudaFuncAttributeMaxDynamicSharedMemorySize, (int)smem);

    int grid = 152;
    if (grid > nIter) grid = nIter;
    qmaml_main_kernel<<<grid, 256, smem>>>(x, W1, b1, ln_g, ln_b, W2, b2, bc,
                                           out, nIter);
}

// round 10
// speedup vs baseline: 1.0265x; 1.0130x over previous
#include <cuda_runtime.h>
#include <math.h>

#define NQ   6
#define DIM  64
#define SPT  256        // samples per iteration per CTA (32 per warp)
#define PW   72         // weight pitch (words), half-shift layout
#define PAX  264        // X tile pitch: 256 cols + 8 mirror
#define PAP  256        // psi tile pitch (no pad needed: offsets stay multiples of 8)

typedef unsigned long long ull;

__device__ float g_CRT[DIM * DIM];   // [j][i]
__device__ float g_CIT[DIM * DIM];   // [j][i]
__device__ float g_Mz[5 * DIM];      // [o][i]
__device__ float g_W2g[NQ * DIM];    // W2[q][i] * ln_g[i]
__device__ float g_Sg[NQ];           // sum_i W2[q][i]*g[i]
__device__ float g_Cq[NQ];           // sum_i be[i]*W2[q][i] + b2[q]

__device__ __forceinline__ void ffma2(ull &d, ull a, ull b) {
    asm("fma.rn.f32x2 %0, %1, %2, %0;" : "+l"(d) : "l"(a), "l"(b));
}
__device__ __forceinline__ ull dup2(float v) {
    ull r; asm("mov.b64 %0, {%1, %1};" : "=l"(r) : "f"(v)); return r;
}
// half-shift: words i>=32 shifted +4 so 8 lanes at 32B stride hit distinct bank quads
__device__ __forceinline__ int ish(int i) { return i + ((i >> 5) << 2); }

__device__ __forceinline__ float fast_tanh(float x) {
    float e = __expf(-2.f * fabsf(x));
    float t = __fdividef(1.f - e, 1.f + e);
    return copysignf(t, x);
}

__device__ __forceinline__ int ring_map(int r, int i) {
    int v = i;
    for (int w = NQ - 1; w >= 0; --w) {
        int t = (w + r) % NQ;
        v ^= ((v >> (NQ - 1 - w)) & 1) << (NQ - 1 - t);
    }
    return v;
}

// One block, 64 threads. Thread j owns column j of C.
__global__ void setup_kernel(const float* __restrict__ th_sh,
                             const float* __restrict__ th_tk,
                             const float* __restrict__ Wc,
                             const float* __restrict__ W2,
                             const float* __restrict__ lng,
                             const float* __restrict__ lnb,
                             const float* __restrict__ b2) {
    __shared__ float2 C[DIM][DIM];
    int j = threadIdx.x;
    if (j >= DIM) return;
    for (int i = 0; i < DIM; i++) C[i][j] = make_float2(i == j ? 1.f : 0.f, 0.f);

    const float* TH[3] = { th_sh, th_sh + NQ * 3, th_tk };
    const int    RS[3] = { 1, 2, 1 };

    for (int l = 0; l < 3; l++) {
        const float* th = TH[l];
        for (int w = 0; w < NQ; w++) {
            float phi = th[w * 3 + 0], te = th[w * 3 + 1], om = th[w * 3 + 2];
            float sth, cth; sincosf(0.5f * te, &sth, &cth);
            float a = 0.5f * (phi + om), b = 0.5f * (phi - om);
            float sa, ca, sb, cb;
            sincosf(a, &sa, &ca);
            sincosf(b, &sb, &cb);
            float2 R00 = make_float2( ca * cth, -sa * cth);
            float2 R01 = make_float2(-cb * sth, -sb * sth);
            float2 R10 = make_float2( cb * sth, -sb * sth);
            float2 R11 = make_float2( ca * cth,  sa * cth);
            int bit = 1 << (NQ - 1 - w);
            for (int i0 = 0; i0 < DIM; i0++) {
                if (i0 & bit) continue;
                int i1 = i0 | bit;
                float2 v0 = C[i0][j], v1 = C[i1][j];
                C[i0][j] = make_float2(
                    R00.x * v0.x - R00.y * v0.y + R01.x * v1.x - R01.y * v1.y,
                    R00.x * v0.y + R00.y * v0.x + R01.x * v1.y + R01.y * v1.x);
                C[i1][j] = make_float2(
                    R10.x * v0.x - R10.y * v0.y + R11.x * v1.x - R11.y * v1.y,
                    R10.x * v0.y + R10.y * v0.x + R11.x * v1.y + R11.y * v1.x);
            }
        }
        float2 tmp[DIM];
        for (int i = 0; i < DIM; i++) tmp[i] = C[ring_map(RS[l], i)][j];
        for (int i = 0; i < DIM; i++) C[i][j] = tmp[i];
    }
    for (int i = 0; i < DIM; i++) {
        g_CRT[j * DIM + i] = C[i][j].x;
        g_CIT[j * DIM + i] = C[i][j].y;
    }
    for (int o = 0; o < 5; o++) {
        float s = 0.f;
        for (int q = 0; q < NQ; q++) {
            float zs = ((j >> (NQ - 1 - q)) & 1) ? -1.f : 1.f;
            s += zs * Wc[o * NQ + q];
        }
        g_Mz[o * DIM + j] = s;
    }
    // LayerNorm-fold constants
    for (int q = 0; q < NQ; q++)
        g_W2g[q * DIM + j] = W2[q * DIM + j] * lng[j];
    if (j < NQ) {
        float sg = 0.f, cq = b2[j];
        for (int i = 0; i < DIM; i++) {
            sg += W2[j * DIM + i] * lng[i];
            cq += lnb[i] * W2[j * DIM + i];
        }
        g_Sg[j] = sg;
        g_Cq[j] = cq;
    }
}

// smem layout (floats)
#define OFF_W1T  0
#define OFF_CRT  (OFF_W1T + DIM * PW)          // 4608
#define OFF_CIT  (OFF_CRT + DIM * PW)          // 9216
#define OFF_W2G  (OFF_CIT + DIM * PW)          // 13824
#define OFF_MZT  (OFF_W2G + NQ * PW)           // 14256
#define OFF_B1   (OFF_MZT + 5 * PW)            // 14616
#define OFF_BC   (OFF_B1 + DIM)                // 14680
#define OFF_SG   (OFF_BC + 8)                  // 14688
#define OFF_CQ   (OFF_SG + 8)                  // 14696
#define OFF_ATX  (OFF_CQ + 8)                  // 14704 (mult of 4 -> 16B aligned)
#define OFF_ATP  (OFF_ATX + DIM * PAX)         // 31600
#define SMEM_FLOATS (OFF_ATP + DIM * PAP)      // 47984 -> ~192 KB

// transpose-reduce: sum v[s] over 8 tx lanes; lane tx returns value for s == tx
__device__ __forceinline__ float txreduce8(float* v, int tx) {
    #pragma unroll
    for (int a = 0; a < 8; a++) v[a] += __shfl_xor_sync(0xffffffffu, v[a], 4);
    float v4[4];
    #pragma unroll
    for (int a = 0; a < 4; a++) v4[a] = (tx & 4) ? v[4 + a] : v[a];
    #pragma unroll
    for (int a = 0; a < 4; a++) v4[a] += __shfl_xor_sync(0xffffffffu, v4[a], 2);
    float v2[2];
    #pragma unroll
    for (int a = 0; a < 2; a++) v2[a] = (tx & 2) ? v4[2 + a] : v4[a];
    #pragma unroll
    for (int a = 0; a < 2; a++) v2[a] += __shfl_xor_sync(0xffffffffu, v2[a], 1);
    return (tx & 1) ? v2[1] : v2[0];
}

__global__ __launch_bounds__(256, 1)
void qmaml_main_kernel(const float* __restrict__ x,
                       const float* __restrict__ W1,
                       const float* __restrict__ b1,
                       const float* __restrict__ bc,
                       float* __restrict__ out,
                       int nIter) {
    extern __shared__ float sm[];
    float* sW1T = sm + OFF_W1T;   // [j][ish(i)]
    float* sCRT = sm + OFF_CRT;
    float* sCIT = sm + OFF_CIT;
    float* sW2g = sm + OFF_W2G;   // [q][ish(i)]
    float* sMzT = sm + OFF_MZT;   // [o][ish(i)]
    float* sB1  = sm + OFF_B1;
    float* sBc  = sm + OFF_BC;
    float* sSg  = sm + OFF_SG;
    float* sCq  = sm + OFF_CQ;
    float* sATX = sm + OFF_ATX;   // [j][(s + 2*(j>>2)) & 255], pitch 264, 8 mirror cols
    float* sATP = sm + OFF_ATP;   // [j][(s + 8*((j>>2)&3)) & 255], pitch 256

    const int tid = threadIdx.x;

    // ---- load shared weights once (whole CTA) ----
    for (int idx = tid; idx < DIM * DIM; idx += 256) {
        int j = idx >> 6, i = idx & 63;
        int d = j * PW + ish(i);
        sW1T[d] = W1[i * DIM + j];    // W1 [i][j] row-major -> [j][i]
        sCRT[d] = g_CRT[idx];         // already [j][i]
        sCIT[d] = g_CIT[idx];
    }
    for (int idx = tid; idx < 5 * DIM; idx += 256) {
        int o = idx >> 6, i = idx & 63;
        sMzT[o * PW + ish(i)] = g_Mz[idx];
    }
    for (int idx = tid; idx < NQ * DIM; idx += 256) {
        int q = idx >> 6, i = idx & 63;
        sW2g[q * PW + ish(i)] = g_W2g[idx];
    }
    if (tid < DIM) sB1[tid] = b1[tid];
    if (tid < NQ) { sSg[tid] = g_Sg[tid]; sCq[tid] = g_Cq[tid]; }
    if (tid < 5) sBc[tid] = bc[tid];
    __syncthreads();

    const int w   = tid >> 5;           // warp 0..7  -> samples 32w..32w+31
    const int l   = tid & 31;           // lane
    const int tx  = l & 7;              // i-lane within octet
    const int oct = l >> 3;             // octet 0..3
    const int s0g = 32 * w + 8 * oct;   // first sample of this thread's 8
    const int i0  = tx * 8;
    const int ish0 = ish(i0);

    for (int iter = blockIdx.x; iter < nIter; iter += gridDim.x) {
        const float4* xg4 = (const float4*)(x + ((size_t)iter * SPT + 32 * w) * DIM);

        __syncwarp();   // all lanes past previous iter's reads of sATX/sATP

        // ---- stage this warp's 32 samples into sATX (coalesced LDG, CF STS) ----
        #pragma unroll
        for (int m = 0; m < 16; m++) {
            int idx = m * 32 + l;                // 512 float4 per warp
            float4 v = xg4[idx];
            int sl = idx >> 4;                   // local sample 0..31
            int j0 = (idx & 15) << 2;            // row group
            int col = (32 * w + sl + (j0 >> 1)) & 255;   // rot_X = 2*(j0>>2) = j0>>1
            float* p = sATX + col;
            p[(j0 + 0) * PAX] = v.x;
            p[(j0 + 1) * PAX] = v.y;
            p[(j0 + 2) * PAX] = v.z;
            p[(j0 + 3) * PAX] = v.w;
            if (col < 8) {
                float* pm = p + 256;
                pm[(j0 + 0) * PAX] = v.x;
                pm[(j0 + 1) * PAX] = v.y;
                pm[(j0 + 2) * PAX] = v.z;
                pm[(j0 + 3) * PAX] = v.w;
            }
        }
        __syncwarp();

        // ---- GEMM1: acc[s][ipair] over j ----
        ull acc[8][4];
        #pragma unroll
        for (int s = 0; s < 8; s++)
            #pragma unroll
            for (int q = 0; q < 4; q++) acc[s][q] = 0ull;

        #pragma unroll 4
        for (int j = 0; j < DIM; j++) {
            int c = (s0g + 2 * (j >> 2)) & 255;
            const float* ap = sATX + j * PAX + c;
            float2 a01 = *(const float2*)(ap);
            float2 a23 = *(const float2*)(ap + 2);
            float2 a45 = *(const float2*)(ap + 4);
            float2 a67 = *(const float2*)(ap + 6);
            const float* bp = sW1T + j * PW + ish0;
            ulonglong2 b01 = *(const ulonglong2*)bp;
            ulonglong2 b23 = *(const ulonglong2*)(bp + 4);
            ull ad[8];
            ad[0] = dup2(a01.x); ad[1] = dup2(a01.y);
            ad[2] = dup2(a23.x); ad[3] = dup2(a23.y);
            ad[4] = dup2(a45.x); ad[5] = dup2(a45.y);
            ad[6] = dup2(a67.x); ad[7] = dup2(a67.y);
            #pragma unroll
            for (int s = 0; s < 8; s++) {
                ffma2(acc[s][0], ad[s], b01.x);
                ffma2(acc[s][1], ad[s], b01.y);
                ffma2(acc[s][2], ad[s], b23.x);
                ffma2(acc[s][3], ad[s], b23.y);
            }
        }

        // ---- bias + relu; LN stats + z-dots on RAW h (LN folded into z) ----
        float h[8][8];
        {
            float bb[8];
            #pragma unroll
            for (int c = 0; c < 8; c++) bb[c] = sB1[i0 + c];
            #pragma unroll
            for (int s = 0; s < 8; s++)
                #pragma unroll
                for (int q = 0; q < 4; q++) {
                    float2 f = *(float2*)&acc[s][q];
                    h[s][2 * q]     = fmaxf(f.x + bb[2 * q], 0.f);
                    h[s][2 * q + 1] = fmaxf(f.y + bb[2 * q + 1], 0.f);
                }
        }
        float vec[12];
        {
            float su[8], sq[8], zp[8][NQ];
            #pragma unroll
            for (int s = 0; s < 8; s++) {
                float a = 0.f, b = 0.f;
                #pragma unroll
                for (int c = 0; c < 8; c++) { a += h[s][c]; b += h[s][c] * h[s][c]; }
                su[s] = a; sq[s] = b;
            }
            #pragma unroll
            for (int q = 0; q < NQ; q++) {
                const float* wp = sW2g + q * PW + ish0;
                float4 wa = *(const float4*)wp;
                float4 wb = *(const float4*)(wp + 4);
                float ww[8] = { wa.x, wa.y, wa.z, wa.w, wb.x, wb.y, wb.z, wb.w };
                #pragma unroll
                for (int s = 0; s < 8; s++) {
                    float d = 0.f;
                    #pragma unroll
                    for (int c = 0; c < 8; c++) d += h[s][c] * ww[c];
                    zp[s][q] = d;
                }
            }
            // reduce 8 quantities across tx lanes; lane tx owns sample s0g+tx = 32w+l
            float S = txreduce8(su, tx);
            float Q = txreduce8(sq, tx);
            float D[NQ];
            #pragma unroll
            for (int q = 0; q < NQ; q++) {
                float v[8];
                #pragma unroll
                for (int s = 0; s < 8; s++) v[s] = zp[s][q];
                D[q] = txreduce8(v, tx);
            }
            float mu  = S * (1.f / DIM);
            float var = Q * (1.f / DIM) - mu * mu;
            float inv = rsqrtf(var + 1e-5f);
            #pragma unroll
            for (int q = 0; q < NQ; q++) {
                float z  = fast_tanh(inv * (D[q] - mu * sSg[q]) + sCq[q]);
                float hh = 1.5707963267948966f * z;
                float sn, cs;
                __sincosf(hh, &sn, &cs);
                vec[2 * q]     = cs;
                vec[2 * q + 1] = sn;
            }
        }

        // ---- psi0: lane = its own sample (32w + l); build 64 amplitudes ----
        {
            int sg = 32 * w + l;
            float t2[2], t4[4], t8[8], t16[16], t32[32], p6[64];
            t2[0] = vec[0]; t2[1] = vec[1];
            #pragma unroll
            for (int k = 0; k < 2; k++) { t4[2*k] = t2[k]*vec[2]; t4[2*k+1] = t2[k]*vec[3]; }
            #pragma unroll
            for (int k = 0; k < 4; k++) { t8[2*k] = t4[k]*vec[4]; t8[2*k+1] = t4[k]*vec[5]; }
            #pragma unroll
            for (int k = 0; k < 8; k++) { t16[2*k] = t8[k]*vec[6]; t16[2*k+1] = t8[k]*vec[7]; }
            #pragma unroll
            for (int k = 0; k < 16; k++) { t32[2*k] = t16[k]*vec[8]; t32[2*k+1] = t16[k]*vec[9]; }
            #pragma unroll
            for (int k = 0; k < 32; k++) { p6[2*k] = t32[k]*vec[10]; p6[2*k+1] = t32[k]*vec[11]; }
            #pragma unroll
            for (int j = 0; j < DIM; j++) {
                int col = (sg + ((j >> 2) & 3) * 8) & 255;
                sATP[j * PAP + col] = p6[j];
            }
        }
        __syncwarp();

        // ---- GEMM2/3: psiR/psiI = psi0 @ C^T ----
        ull aR[8][4], aI[8][4];
        #pragma unroll
        for (int s = 0; s < 8; s++)
            #pragma unroll
            for (int q = 0; q < 4; q++) { aR[s][q] = 0ull; aI[s][q] = 0ull; }

        #pragma unroll 4
        for (int j = 0; j < DIM; j++) {
            int c = (s0g + ((j >> 2) & 3) * 8) & 255;
            const float* ap = sATP + j * PAP + c;
            float4 al = *(const float4*)ap;
            float4 ah = *(const float4*)(ap + 4);
            const float* rp = sCRT + j * PW + ish0;
            const float* ip = sCIT + j * PW + ish0;
            ulonglong2 r01 = *(const ulonglong2*)rp;
            ulonglong2 r23 = *(const ulonglong2*)(rp + 4);
            ulonglong2 i01 = *(const ulonglong2*)ip;
            ulonglong2 i23 = *(const ulonglong2*)(ip + 4);
            ull ad[8];
            ad[0] = dup2(al.x); ad[1] = dup2(al.y); ad[2] = dup2(al.z); ad[3] = dup2(al.w);
            ad[4] = dup2(ah.x); ad[5] = dup2(ah.y); ad[6] = dup2(ah.z); ad[7] = dup2(ah.w);
            #pragma unroll
            for (int s = 0; s < 8; s++) {
                ffma2(aR[s][0], ad[s], r01.x);
                ffma2(aR[s][1], ad[s], r01.y);
                ffma2(aR[s][2], ad[s], r23.x);
                ffma2(aR[s][3], ad[s], r23.y);
                ffma2(aI[s][0], ad[s], i01.x);
                ffma2(aI[s][1], ad[s], i01.y);
                ffma2(aI[s][2], ad[s], i23.x);
                ffma2(aI[s][3], ad[s], i23.y);
            }
        }

        // ---- probs -> Mz partials -> transpose-reduce -> gmem ----
        {
            ulonglong2 mza[5], mzb[5];
            #pragma unroll
            for (int o = 0; o < 5; o++) {
                const float* mp = sMzT + o * PW + ish0;
                mza[o] = *(const ulonglong2*)mp;
                mzb[o] = *(const ulonglong2*)(mp + 4);
            }
            float vals[8][5];
            #pragma unroll
            for (int s = 0; s < 8; s++) {
                ull pp[4];
                #pragma unroll
                for (int q = 0; q < 4; q++) {
                    pp[q] = 0ull;
                    ffma2(pp[q], aR[s][q], aR[s][q]);
                    ffma2(pp[q], aI[s][q], aI[s][q]);
                }
                #pragma unroll
                for (int o = 0; o < 5; o++) {
                    ull a5 = 0ull;
                    ffma2(a5, pp[0], mza[o].x);
                    ffma2(a5, pp[1], mza[o].y);
                    ffma2(a5, pp[2], mzb[o].x);
                    ffma2(a5, pp[3], mzb[o].y);
                    float2 f = *(float2*)&a5;
                    vals[s][o] = f.x + f.y;
                }
            }
            size_t og = ((size_t)iter * SPT + 32 * w + l) * 5;
            #pragma unroll
            for (int o = 0; o < 5; o++) {
                float v[8];
                #pragma unroll
                for (int s = 0; s < 8; s++) v[s] = vals[s][o];
                float r = txreduce8(v, tx);     // lane l gets sample 32w+l
                out[og + o] = r + sBc[o];
            }
        }
    }
}

extern "C" void kernel_launch(void* const* d_in, const int* in_sizes, int n_in,
                              void* d_out, int out_size) {
    const float* x     = (const float*)d_in[0];
    const float* W1    = (const float*)d_in[1];
    const float* b1    = (const float*)d_in[2];
    const float* ln_g  = (const float*)d_in[3];
    const float* ln_b  = (const float*)d_in[4];
    const float* W2    = (const float*)d_in[5];
    const float* b2    = (const float*)d_in[6];
    const float* th_sh = (const float*)d_in[7];
    const float* th_tk = (const float*)d_in[8];
    const float* Wc    = (const float*)d_in[9];
    const float* bc    = (const float*)d_in[10];
    float* out = (float*)d_out;

    int B = in_sizes[0] / DIM;
    int nIter = B / SPT;

    setup_kernel<<<1, 64>>>(th_sh, th_tk, Wc, W2, ln_g, ln_b, b2);

    size_t smem = (size_t)SMEM_FLOATS * sizeof(float);
    cudaFuncSetAttribute(qmaml_main_kernel,
                         cudaFuncAttributeMaxDynamicSharedMemorySize, (int)smem);

    int grid = 128;                  // 512 tiles / 128 blocks = 4 each, balanced
    if (grid > nIter) grid = nIter;
    qmaml_main_kernel<<<grid, 256, smem>>>(x, W1, b1, bc, out, nIter);
}